// round 2
// baseline (speedup 1.0000x reference)
#include <cuda_runtime.h>
#include <math.h>

#define D   256
#define NPN 128           // nodes per batch
#define BB  8
#define GN  (BB*NPN)      // 1024 (b,i) pairs

typedef unsigned long long u64;

// ---------- packed f32x2 helpers (FFMA2) ----------
__device__ __forceinline__ u64 pk2(float x, float y){
    u64 r; asm("mov.b64 %0, {%1,%2};" : "=l"(r) : "f"(x), "f"(y)); return r;
}
__device__ __forceinline__ void upk2(u64 v, float &x, float &y){
    asm("mov.b64 {%0,%1}, %2;" : "=f"(x), "=f"(y) : "l"(v));
}
__device__ __forceinline__ void fma2(u64 &d, u64 a, u64 b){
    asm("fma.rn.f32x2 %0, %1, %2, %0;" : "+l"(d) : "l"(a), "l"(b));
}
__device__ __forceinline__ float silu_f(float v){ return __fdividef(v, 1.f + __expf(-v)); }
__device__ __forceinline__ float sigm_f(float v){ return __fdividef(1.f, 1.f + __expf(-v)); }

// ---------- scratch (no allocations allowed) ----------
__device__ float g_PiE[GN*D];
__device__ float g_PjE[GN*D];
__device__ float g_PiX[GN*D];
__device__ float g_PjX[GN*D];
__device__ float g_msg[GN*D];

// =====================================================================
// Kernel A: node projections  Pi/Pj for both e- and x-chains
//   Pi_e = inv @ W_e1[0:256]   + b_e1   (bias folded once, matches ref)
//   Pj_e = inv @ W_e1[256:512]
// =====================================================================
__global__ void proj_kernel(const float* __restrict__ inv,
                            const float* __restrict__ We1, const float* __restrict__ be1,
                            const float* __restrict__ Wx1, const float* __restrict__ bx1)
{
    __shared__ float invs[D];
    int g = blockIdx.x; int c = threadIdx.x;
    invs[c] = inv[g*D + c];
    __syncthreads();
    float aie = be1[c], aje = 0.f, aix = bx1[c], ajx = 0.f;
    #pragma unroll 4
    for (int k = 0; k < D; ++k){
        float v = invs[k];
        aie += v * We1[k*D + c];
        aje += v * We1[(D + k)*D + c];
        aix += v * Wx1[k*D + c];
        ajx += v * Wx1[(D + k)*D + c];
    }
    g_PiE[g*D+c] = aie; g_PjE[g*D+c] = aje;
    g_PiX[g*D+c] = aix; g_PjX[g*D+c] = ajx;
}

// =====================================================================
// Kernel B: fused per-edge MLPs. One CTA per (b,i); loops j in 2 tiles
// of 64. Thread tile: 4 j  x  16 channels (channels strided: c=2cg+32t
// so SMEM weight reads are conflict-free LDS.64).
// =====================================================================
#define TJ   64
#define ESTR 260       // E1/X1 row stride (pad kills j-stride conflicts)
#define FSTR 68        // f row stride (65 used, float4-aligned)

// SMEM float counts
#define SM_E1   (TJ*ESTR)
#define SM_WS   (64*D)
#define SM_FS   (TJ*FSTR)
#define SMEM_FLOATS (2*SM_E1 + SM_WS + SM_FS + 4*D + TJ*3 + TJ + TJ + D + 8)
#define SMEM_BYTES  (SMEM_FLOATS*4)

__global__ void __launch_bounds__(256, 1)
edge_kernel(const float* __restrict__ coords, const float* __restrict__ adj,
            const float* __restrict__ amask,  const float* __restrict__ ef,
            const float* __restrict__ We1,    const float* __restrict__ We2,
            const float* __restrict__ be2,    const float* __restrict__ Watt,
            const float* __restrict__ batt,
            const float* __restrict__ Wx1,    const float* __restrict__ Wx2,
            const float* __restrict__ bx2,    const float* __restrict__ Wx3,
            const float* __restrict__ bx3,
            float* __restrict__ outc)
{
    extern __shared__ float sm[];
    float* E1s   = sm;                    // [64][260]
    float* X1s   = E1s  + SM_E1;          // [64][260]
    float* Ws    = X1s  + SM_E1;          // [64][256]  streamed weight chunk
    float* fs    = Ws   + SM_WS;          // [64][68]
    float* PiE   = fs   + SM_FS;          // [256]
    float* PiX   = PiE  + D;              // [256]
    float* WattS = PiX  + D;              // [256]
    float* Wx3S  = WattS+ D;              // [256]
    float* dif   = Wx3S + D;              // [64*3]
    float* rns   = dif  + TJ*3;           // [64]
    float* adjv  = rns  + TJ;             // [64]
    float* msgS  = adjv + TJ;             // [256]
    float* crdS  = msgS + D;              // [3]
    float* nnS   = crdS + 4;              // [1]

    const int gi  = blockIdx.x;
    const int b   = gi >> 7;
    const int tid = threadIdx.x;
    const int cg  = tid & 15;             // channel group
    const int jg  = tid >> 4;             // j group
    const int cb  = 2*cg;                 // c = cb + 32*t
    const int j0  = jg*4;

    PiE[tid]   = g_PiE[gi*D + tid];
    PiX[tid]   = g_PiX[gi*D + tid];
    WattS[tid] = Watt[tid];
    Wx3S[tid]  = Wx3[tid];
    msgS[tid]  = 0.f;
    if (tid < 4) crdS[tid] = 0.f;
    if (tid == 0) nnS[0] = 1.f;
    __syncthreads();
    if (tid < NPN) atomicAdd(nnS, amask[b*NPN + tid]);

    const float battv = batt[0];
    const float bx3v  = bx3[0];
    const float cx = coords[gi*3+0], cy = coords[gi*3+1], cz = coords[gi*3+2];

    float msgA[16];
    #pragma unroll
    for (int q = 0; q < 16; ++q) msgA[q] = 0.f;
    float cacc0 = 0.f, cacc1 = 0.f, cacc2 = 0.f;

    for (int tile = 0; tile < 2; ++tile){
        const int J0 = tile*TJ;
        __syncthreads();   // protect fs/E1s/X1s/dif vs previous tile readers

        // ---- build f (edge_feats + squared distance), diffs, norms ----
        {
            int j = tid >> 2, q = (tid & 3) * 16;
            const float4* src = (const float4*)(ef + ((size_t)gi*NPN + J0 + j)*64 + q);
            float4* dst = (float4*)(fs + j*FSTR + q);
            dst[0] = src[0]; dst[1] = src[1]; dst[2] = src[2]; dst[3] = src[3];
        }
        if (tid < TJ){
            int j = tid;
            const float* cj = coords + (size_t)(b*NPN + J0 + j)*3;
            float dx = cx - cj[0], dy = cy - cj[1], dz = cz - cj[2];
            float sq = dx*dx + dy*dy + dz*dz;
            dif[j*3+0] = dx; dif[j*3+1] = dy; dif[j*3+2] = dz;
            fs[j*FSTR + 64] = sq;
            rns[j]  = __fdividef(1.f, sqrtf(sq + 1e-5f) + 1.f);
            adjv[j] = adj[(size_t)gi*NPN + J0 + j];
        }
        __syncthreads();

        // ---- Stage A: chain-1 (65 -> 256) for both chains, silu, to SMEM ----
        #pragma unroll 1
        for (int which = 0; which < 2; ++which){
            const float* Wp = (which ? Wx1 : We1) + 512*D;   // edge rows of W
            const float* Pi = which ? PiX : PiE;
            const float* Pj = which ? g_PjX : g_PjE;
            float* Os       = which ? X1s : E1s;

            u64 acc[4][8];
            #pragma unroll
            for (int r = 0; r < 4; ++r){
                const float* pj = Pj + (size_t)(b*NPN + J0 + j0 + r)*D;
                #pragma unroll
                for (int t = 0; t < 8; ++t){
                    int c = cb + 32*t;
                    acc[r][t] = pk2(Pi[c] + pj[c], Pi[c+1] + pj[c+1]);
                }
            }
            for (int k = 0; k < 65; ++k){
                u64 fb[4];
                #pragma unroll
                for (int r = 0; r < 4; ++r){
                    float fv = fs[(j0+r)*FSTR + k]; fb[r] = pk2(fv, fv);
                }
                const float* wrow = Wp + k*D;
                #pragma unroll
                for (int t = 0; t < 8; ++t){
                    u64 w = *(const u64*)(wrow + cb + 32*t);
                    fma2(acc[0][t], fb[0], w); fma2(acc[1][t], fb[1], w);
                    fma2(acc[2][t], fb[2], w); fma2(acc[3][t], fb[3], w);
                }
            }
            #pragma unroll
            for (int r = 0; r < 4; ++r)
                #pragma unroll
                for (int t = 0; t < 8; ++t){
                    float x, y; upk2(acc[r][t], x, y);
                    int c = cb + 32*t;
                    float2 s; s.x = silu_f(x); s.y = silu_f(y);
                    *(float2*)&Os[(j0+r)*ESTR + c] = s;
                }
        }
        __syncthreads();

        // ---- Chain-2 E: M = silu(E1 @ We2 + b), att, msg accumulation ----
        {
            u64 acc[4][8];
            #pragma unroll
            for (int t = 0; t < 8; ++t){
                int c = cb + 32*t;
                u64 bi = pk2(be2[c], be2[c+1]);
                acc[0][t]=bi; acc[1][t]=bi; acc[2][t]=bi; acc[3][t]=bi;
            }
            for (int kc = 0; kc < 4; ++kc){
                __syncthreads();
                const float4* src = (const float4*)(We2 + (size_t)kc*64*D);
                float4* dst = (float4*)Ws;
                #pragma unroll
                for (int r = 0; r < 16; ++r) dst[tid + r*256] = src[tid + r*256];
                __syncthreads();
                for (int k = 0; k < 64; ++k){
                    int kk = kc*64 + k;
                    u64 eb[4];
                    #pragma unroll
                    for (int r = 0; r < 4; ++r){
                        float v = E1s[(j0+r)*ESTR + kk]; eb[r] = pk2(v, v);
                    }
                    const float* wrow = Ws + k*D;
                    #pragma unroll
                    for (int t = 0; t < 8; ++t){
                        u64 w = *(const u64*)(wrow + cb + 32*t);
                        fma2(acc[0][t], eb[0], w); fma2(acc[1][t], eb[1], w);
                        fma2(acc[2][t], eb[2], w); fma2(acc[3][t], eb[3], w);
                    }
                }
            }
            #pragma unroll
            for (int r = 0; r < 4; ++r){
                float m[16]; float ap = 0.f;
                #pragma unroll
                for (int t = 0; t < 8; ++t){
                    float x, y; upk2(acc[r][t], x, y);
                    x = silu_f(x); y = silu_f(y);
                    int c = cb + 32*t;
                    m[2*t] = x; m[2*t+1] = y;
                    ap += x*WattS[c] + y*WattS[c+1];
                }
                ap += __shfl_xor_sync(0xffffffffu, ap, 1);
                ap += __shfl_xor_sync(0xffffffffu, ap, 2);
                ap += __shfl_xor_sync(0xffffffffu, ap, 4);
                ap += __shfl_xor_sync(0xffffffffu, ap, 8);
                int lj = j0 + r;
                float wgt = sigm_f(ap + battv) * adjv[lj];
                #pragma unroll
                for (int q = 0; q < 16; ++q) msgA[q] += m[q]*wgt;
            }
        }

        // ---- Chain-2 X: X2 = silu(X1 @ Wx2 + b), edge_attn, coord accum ----
        {
            u64 acc[4][8];
            #pragma unroll
            for (int t = 0; t < 8; ++t){
                int c = cb + 32*t;
                u64 bi = pk2(bx2[c], bx2[c+1]);
                acc[0][t]=bi; acc[1][t]=bi; acc[2][t]=bi; acc[3][t]=bi;
            }
            for (int kc = 0; kc < 4; ++kc){
                __syncthreads();
                const float4* src = (const float4*)(Wx2 + (size_t)kc*64*D);
                float4* dst = (float4*)Ws;
                #pragma unroll
                for (int r = 0; r < 16; ++r) dst[tid + r*256] = src[tid + r*256];
                __syncthreads();
                for (int k = 0; k < 64; ++k){
                    int kk = kc*64 + k;
                    u64 eb[4];
                    #pragma unroll
                    for (int r = 0; r < 4; ++r){
                        float v = X1s[(j0+r)*ESTR + kk]; eb[r] = pk2(v, v);
                    }
                    const float* wrow = Ws + k*D;
                    #pragma unroll
                    for (int t = 0; t < 8; ++t){
                        u64 w = *(const u64*)(wrow + cb + 32*t);
                        fma2(acc[0][t], eb[0], w); fma2(acc[1][t], eb[1], w);
                        fma2(acc[2][t], eb[2], w); fma2(acc[3][t], eb[3], w);
                    }
                }
            }
            #pragma unroll
            for (int r = 0; r < 4; ++r){
                float ap = 0.f;
                #pragma unroll
                for (int t = 0; t < 8; ++t){
                    float x, y; upk2(acc[r][t], x, y);
                    x = silu_f(x); y = silu_f(y);
                    int c = cb + 32*t;
                    ap += x*Wx3S[c] + y*Wx3S[c+1];
                }
                ap += __shfl_xor_sync(0xffffffffu, ap, 1);
                ap += __shfl_xor_sync(0xffffffffu, ap, 2);
                ap += __shfl_xor_sync(0xffffffffu, ap, 4);
                ap += __shfl_xor_sync(0xffffffffu, ap, 8);
                int lj = j0 + r;
                float wgt = (ap + bx3v) * rns[lj] * adjv[lj];
                if (cg == 0){
                    cacc0 += dif[lj*3+0]*wgt;
                    cacc1 += dif[lj*3+1]*wgt;
                    cacc2 += dif[lj*3+2]*wgt;
                }
            }
        }
    } // tile loop

    // ---- flush per-thread accumulators ----
    #pragma unroll
    for (int t = 0; t < 8; ++t){
        int c = cb + 32*t;
        atomicAdd(&msgS[c],   msgA[2*t]);
        atomicAdd(&msgS[c+1], msgA[2*t+1]);
    }
    if (cg == 0){
        atomicAdd(&crdS[0], cacc0);
        atomicAdd(&crdS[1], cacc1);
        atomicAdd(&crdS[2], cacc2);
    }
    __syncthreads();

    g_msg[gi*D + tid] = msgS[tid];
    if (tid < 3){
        float upd = crdS[tid] / nnS[0];
        outc[gi*3 + tid] = (coords[gi*3 + tid] + upd) * amask[gi];
    }
}

// =====================================================================
// Kernel C: node MLP  h = silu([inv, msg] @ Wh1 + b) @ Wh2 + b ; * mask
// =====================================================================
__global__ void node_kernel(const float* __restrict__ inv, const float* __restrict__ amask,
                            const float* __restrict__ Wh1, const float* __restrict__ bh1,
                            const float* __restrict__ Wh2, const float* __restrict__ bh2,
                            float* __restrict__ outf)
{
    __shared__ float cat[2*D];
    __shared__ float h1[D];
    int g = blockIdx.x, c = threadIdx.x;
    cat[c]     = inv[g*D + c];
    cat[D + c] = g_msg[g*D + c];
    __syncthreads();
    float a = bh1[c];
    #pragma unroll 4
    for (int k = 0; k < 2*D; ++k) a += cat[k] * Wh1[k*D + c];
    h1[c] = silu_f(a);
    __syncthreads();
    float o = bh2[c];
    #pragma unroll 4
    for (int k = 0; k < D; ++k) o += h1[k] * Wh2[k*D + c];
    outf[g*D + c] = o * amask[g];
}

// =====================================================================
extern "C" void kernel_launch(void* const* d_in, const int* in_sizes, int n_in,
                              void* d_out, int out_size)
{
    const float* coords = (const float*)d_in[0];
    const float* inv    = (const float*)d_in[1];
    const float* adj    = (const float*)d_in[2];
    const float* amask  = (const float*)d_in[3];
    const float* ef     = (const float*)d_in[4];
    const float* We1    = (const float*)d_in[5];
    const float* be1    = (const float*)d_in[6];
    const float* We2    = (const float*)d_in[7];
    const float* be2    = (const float*)d_in[8];
    const float* Watt   = (const float*)d_in[9];
    const float* batt   = (const float*)d_in[10];
    const float* Wh1    = (const float*)d_in[11];
    const float* bh1    = (const float*)d_in[12];
    const float* Wh2    = (const float*)d_in[13];
    const float* bh2    = (const float*)d_in[14];
    const float* Wx1    = (const float*)d_in[15];
    const float* bx1    = (const float*)d_in[16];
    const float* Wx2    = (const float*)d_in[17];
    const float* bx2    = (const float*)d_in[18];
    const float* Wx3    = (const float*)d_in[19];
    const float* bx3    = (const float*)d_in[20];

    float* out = (float*)d_out;
    float* outc = out;              // [8,128,3]
    float* outf = out + GN*3;       // [8,128,256]

    cudaFuncSetAttribute(edge_kernel, cudaFuncAttributeMaxDynamicSharedMemorySize, SMEM_BYTES);

    proj_kernel<<<GN, 256>>>(inv, We1, be1, Wx1, bx1);
    edge_kernel<<<GN, 256, SMEM_BYTES>>>(coords, adj, amask, ef,
                                         We1, We2, be2, Watt, batt,
                                         Wx1, Wx2, bx2, Wx3, bx3, outc);
    node_kernel<<<GN, 256>>>(inv, amask, Wh1, bh1, Wh2, bh2, outf);
}

// round 6
// speedup vs baseline: 2.1424x; 2.1424x over previous
#include <cuda_runtime.h>
#include <cuda_bf16.h>
#include <math.h>
#include <stdint.h>

#define D    256
#define NPN  128
#define GN   1024

__device__ __forceinline__ float silu_f(float v){ return __fdividef(v, 1.f + __expf(-v)); }
__device__ __forceinline__ float sigm_f(float v){ return __fdividef(1.f, 1.f + __expf(-v)); }

__device__ float g_PiE[GN*D], g_PjE[GN*D], g_PiX[GN*D], g_PjX[GN*D], g_msg[GN*D];
__device__ __align__(16) float g_W1Te[256*76], g_W1Tx[256*76];     // [n][k], k<65 data, pad 0
__device__ __align__(16) float g_W2Te[256*256], g_W2Tx[256*256];   // [n][k]

// m16n8k8 tf32 mma (legacy tensor path, sm_80+; compiles on sm_100 target)
__device__ __forceinline__ void mma8(float c[4], const uint32_t a[4], uint32_t b0, uint32_t b1){
    asm volatile("mma.sync.aligned.m16n8k8.row.col.f32.tf32.tf32.f32 "
        "{%0,%1,%2,%3},{%4,%5,%6,%7},{%8,%9},{%0,%1,%2,%3};"
        : "+f"(c[0]),"+f"(c[1]),"+f"(c[2]),"+f"(c[3])
        : "r"(a[0]),"r"(a[1]),"r"(a[2]),"r"(a[3]),"r"(b0),"r"(b1));
}

// ---------------- SMEM layout (floats) ----------------
#define FAO   0              // [128][76] f tile (9728) ; reused as bf16 m0 [128][128] in chain-2E
#define W1SO  9728           // [64][76]  W1 slice (4864)
#define W2SO  14592          // [128][36] W2 chunk (4608)
#define E1O   19200          // [128][260] E1/X1 (33280)
#define MB    52480
#define MPI   (MB+0)
#define MB2   (MB+256)
#define MWV   (MB+512)
#define MDX   (MB+768)
#define MDY   (MB+896)
#define MDZ   (MB+1024)
#define MRN   (MB+1152)
#define MAD   (MB+1280)
#define MSQ   (MB+1408)
#define MWG   (MB+1536)
#define MRS   (MB+1664)
#define MMS   (MB+1792)
#define MCR   (MB+2048)
#define MNN   (MB+2052)
#define SM_FLOATS (MB+2056)
#define SMEM_BYTES (SM_FLOATS*4)   // 218144 B

// =====================================================================
// prep: transposed weight operands
// =====================================================================
__global__ void prep_kernel(const float* __restrict__ We1, const float* __restrict__ Wx1,
                            const float* __restrict__ We2, const float* __restrict__ Wx2)
{
    int i = blockIdx.x*blockDim.x + threadIdx.x;
    if (i < 256*76){
        int n = i/76, k = i%76;
        g_W1Te[i] = (k<65) ? We1[(512+k)*D + n] : 0.f;
        g_W1Tx[i] = (k<65) ? Wx1[(512+k)*D + n] : 0.f;
    }
    if (i < 256*256){
        int n = i>>8, k = i&255;
        g_W2Te[i] = We2[k*D + n];
        g_W2Tx[i] = Wx2[k*D + n];
    }
}

// =====================================================================
// proj: node projections (bias folded into Pi), 8 nodes per CTA
// =====================================================================
__global__ void proj_kernel(const float* __restrict__ inv,
                            const float* __restrict__ We1, const float* __restrict__ be1,
                            const float* __restrict__ Wx1, const float* __restrict__ bx1)
{
    __shared__ float invs[8*D];
    int g0 = blockIdx.x*8, c = threadIdx.x;
    #pragma unroll
    for (int r=0;r<8;++r) invs[r*D+c] = inv[(g0+r)*D + c];
    __syncthreads();
    float aie[8], aje[8], aix[8], ajx[8];
    float b1 = be1[c], b2 = bx1[c];
    #pragma unroll
    for (int r=0;r<8;++r){ aie[r]=b1; aje[r]=0.f; aix[r]=b2; ajx[r]=0.f; }
    for (int k=0;k<D;++k){
        float wei = We1[k*D+c], wej = We1[(D+k)*D+c];
        float wxi = Wx1[k*D+c], wxj = Wx1[(D+k)*D+c];
        #pragma unroll
        for (int r=0;r<8;++r){
            float v = invs[r*D+k];
            aie[r] += v*wei; aje[r] += v*wej; aix[r] += v*wxi; ajx[r] += v*wxj;
        }
    }
    #pragma unroll
    for (int r=0;r<8;++r){
        int g = g0+r;
        g_PiE[g*D+c]=aie[r]; g_PjE[g*D+c]=aje[r];
        g_PiX[g*D+c]=aix[r]; g_PjX[g*D+c]=ajx[r];
    }
}

// =====================================================================
// edge kernel: tf32 mma.sync, one CTA per (b,i), M=128 N=256
// =====================================================================
__global__ void __launch_bounds__(256,1)
edge_kernel(const float* __restrict__ coords, const float* __restrict__ adj,
            const float* __restrict__ amask,  const float* __restrict__ ef,
            const float* __restrict__ be2,    const float* __restrict__ Watt,
            const float* __restrict__ batt,   const float* __restrict__ bx2,
            const float* __restrict__ Wx3,    const float* __restrict__ bx3,
            float* __restrict__ outc)
{
    extern __shared__ float sm[];
    const int gi   = blockIdx.x;
    const int bi   = gi >> 7;
    const int tid  = threadIdx.x;
    const int warp = tid >> 5;
    const int lane = tid & 31;
    const int wm   = warp >> 1;       // 0..3  (M groups of 32)
    const int wn   = warp & 1;        // 0..1
    const int qr   = lane >> 2;       // 0..7
    const int qc   = lane & 3;        // 0..3

    // ---- init ----
    sm[MMS + tid] = 0.f;
    if (tid < 4) sm[MCR + tid] = 0.f;
    if (tid == 0) sm[MNN] = 1.f;
    const float cx = coords[gi*3+0], cy = coords[gi*3+1], cz = coords[gi*3+2];
    if (tid < NPN){
        const float* cj = coords + (size_t)(bi*NPN + tid)*3;
        float dx = cx-cj[0], dy = cy-cj[1], dz = cz-cj[2];
        float sq = dx*dx + dy*dy + dz*dz;
        sm[MDX+tid]=dx; sm[MDY+tid]=dy; sm[MDZ+tid]=dz;
        sm[MSQ+tid]=sq;
        sm[MRN+tid]=__fdividef(1.f, sqrtf(sq + 1e-5f) + 1.f);
        sm[MAD+tid]=adj[(size_t)gi*NPN + tid];
    }
    __syncthreads();
    if (tid < NPN) atomicAdd(&sm[MNN], amask[bi*NPN + tid]);
    const float battv = batt[0], bx3v = bx3[0];

    #pragma unroll 1
    for (int ch = 0; ch < 2; ++ch){
        // per-chain constants
        sm[MPI+tid] = ch ? g_PiX[gi*D+tid] : g_PiE[gi*D+tid];
        sm[MB2+tid] = ch ? bx2[tid] : be2[tid];
        sm[MWV+tid] = ch ? Wx3[tid] : Watt[tid];
        if (tid < NPN) sm[MRS+tid] = 0.f;

        // rebuild f tile [128][76]: k<64 = ef, k==64 = sq, else 0
        #pragma unroll 4
        for (int it=0; it<32; ++it){
            int idx = tid + it*256; int j = idx>>6; int k = idx&63;
            sm[FAO + j*76 + k] = ef[((size_t)gi*NPN + j)*64 + k];
        }
        #pragma unroll
        for (int it=0; it<6; ++it){
            int idx = tid + it*256;             // < 1536 = 128*12
            int j = idx/12; int k = 64 + idx%12;
            sm[FAO + j*76 + k] = (k==64) ? sm[MSQ+j] : 0.f;
        }
        __syncthreads();

        const float* W1T = ch ? g_W1Tx : g_W1Te;
        const float* W2T = ch ? g_W2Tx : g_W2Te;
        const float* PjG = ch ? g_PjX  : g_PjE;

        // ---- chain-1: E1 = silu(f @ W1^T + Pi + Pj), 4 n-blocks of 64 ----
        #pragma unroll 1
        for (int nb = 0; nb < 4; ++nb){
            __syncthreads();
            {
                const float4* s4 = (const float4*)(W1T + nb*64*76);
                #pragma unroll
                for (int it=0; it<5; ++it){
                    int p = tid + it*256;
                    if (p < 1216) ((float4*)(sm + W1SO))[p] = s4[p];
                }
            }
            __syncthreads();

            float c1[2][4][4];
            #pragma unroll
            for (int mt=0;mt<2;++mt)
                #pragma unroll
                for (int nt=0;nt<4;++nt)
                    #pragma unroll
                    for (int q=0;q<4;++q) c1[mt][nt][q]=0.f;

            #pragma unroll
            for (int ks=0; ks<9; ++ks){
                int k0 = ks*8;
                uint32_t a[2][4];
                #pragma unroll
                for (int mt=0;mt<2;++mt){
                    int rb = wm*32 + mt*16 + qr;
                    a[mt][0] = __float_as_uint(sm[FAO + rb*76     + k0+qc]);
                    a[mt][1] = __float_as_uint(sm[FAO + (rb+8)*76 + k0+qc]);
                    a[mt][2] = __float_as_uint(sm[FAO + rb*76     + k0+qc+4]);
                    a[mt][3] = __float_as_uint(sm[FAO + (rb+8)*76 + k0+qc+4]);
                }
                #pragma unroll
                for (int nt=0;nt<4;++nt){
                    int nl = wn*32 + nt*8 + qr;
                    uint32_t b0 = __float_as_uint(sm[W1SO + nl*76 + k0+qc]);
                    uint32_t b1 = __float_as_uint(sm[W1SO + nl*76 + k0+qc+4]);
                    mma8(c1[0][nt], a[0], b0, b1);
                    mma8(c1[1][nt], a[1], b0, b1);
                }
            }
            // epilogue 1: + Pi + Pj, silu -> E1
            #pragma unroll
            for (int mt=0;mt<2;++mt){
                int row = wm*32 + mt*16 + qr;
                #pragma unroll
                for (int nt=0;nt<4;++nt){
                    int colg = nb*64 + wn*32 + nt*8 + 2*qc;
                    const float* pjr = PjG + ((size_t)(bi*NPN)+row)*D + colg;
                    float2 p0 = *(const float2*)pjr;
                    float2 p8 = *(const float2*)(pjr + 8*D);
                    float pi0 = sm[MPI+colg], pi1 = sm[MPI+colg+1];
                    float2 e0, e8;
                    e0.x = silu_f(c1[mt][nt][0] + pi0 + p0.x);
                    e0.y = silu_f(c1[mt][nt][1] + pi1 + p0.y);
                    e8.x = silu_f(c1[mt][nt][2] + pi0 + p8.x);
                    e8.y = silu_f(c1[mt][nt][3] + pi1 + p8.y);
                    *(float2*)&sm[E1O + row*260 + colg]     = e0;
                    *(float2*)&sm[E1O + (row+8)*260 + colg] = e8;
                }
            }
        }
        __syncthreads();

        // ---- chain-2: D2 = E1 @ W2^T, two n-halves of 128 ----
        #pragma unroll 1
        for (int nh = 0; nh < 2; ++nh){
            float c2[2][8][4];
            #pragma unroll
            for (int mt=0;mt<2;++mt)
                #pragma unroll
                for (int nt=0;nt<8;++nt)
                    #pragma unroll
                    for (int q=0;q<4;++q) c2[mt][nt][q]=0.f;

            #pragma unroll 1
            for (int kc = 0; kc < 8; ++kc){
                __syncthreads();
                #pragma unroll
                for (int it=0; it<4; ++it){
                    int p = tid + it*256;           // < 1024
                    int r = p >> 3, cc = p & 7;
                    ((float4*)(sm + W2SO))[r*9 + cc] =
                        ((const float4*)(W2T + ((size_t)(nh*128 + r))*256 + kc*32))[cc];
                }
                __syncthreads();

                #pragma unroll
                for (int ks=0; ks<4; ++ks){
                    int kg = kc*32 + ks*8;          // global k into E1
                    int kl = ks*8;                  // local k into chunk
                    uint32_t a[2][4];
                    #pragma unroll
                    for (int mt=0;mt<2;++mt){
                        int rb = wm*32 + mt*16 + qr;
                        a[mt][0] = __float_as_uint(sm[E1O + rb*260     + kg+qc]);
                        a[mt][1] = __float_as_uint(sm[E1O + (rb+8)*260 + kg+qc]);
                        a[mt][2] = __float_as_uint(sm[E1O + rb*260     + kg+qc+4]);
                        a[mt][3] = __float_as_uint(sm[E1O + (rb+8)*260 + kg+qc+4]);
                    }
                    #pragma unroll
                    for (int nt=0;nt<8;++nt){
                        int nl = wn*64 + nt*8 + qr;
                        uint32_t b0 = __float_as_uint(sm[W2SO + nl*36 + kl+qc]);
                        uint32_t b1 = __float_as_uint(sm[W2SO + nl*36 + kl+qc+4]);
                        mma8(c2[0][nt], a[0], b0, b1);
                        mma8(c2[1][nt], a[1], b0, b1);
                    }
                }
            }

            // rowsum partials: dot(silu(D2+b2), wv) over this half's cols
            #pragma unroll
            for (int mt=0;mt<2;++mt){
                float pr0 = 0.f, pr8 = 0.f;
                #pragma unroll
                for (int nt=0;nt<8;++nt){
                    int colg = nh*128 + wn*64 + nt*8 + 2*qc;
                    float b0 = sm[MB2+colg], b1c = sm[MB2+colg+1];
                    float w0 = sm[MWV+colg], w1 = sm[MWV+colg+1];
                    pr0 += silu_f(c2[mt][nt][0]+b0)*w0 + silu_f(c2[mt][nt][1]+b1c)*w1;
                    pr8 += silu_f(c2[mt][nt][2]+b0)*w0 + silu_f(c2[mt][nt][3]+b1c)*w1;
                }
                pr0 += __shfl_xor_sync(0xffffffffu, pr0, 1);
                pr0 += __shfl_xor_sync(0xffffffffu, pr0, 2);
                pr8 += __shfl_xor_sync(0xffffffffu, pr8, 1);
                pr8 += __shfl_xor_sync(0xffffffffu, pr8, 2);
                if (qc == 0){
                    atomicAdd(&sm[MRS + wm*32 + mt*16 + qr],     pr0);
                    atomicAdd(&sm[MRS + wm*32 + mt*16 + qr + 8], pr8);
                }
            }

            // chain E half-0: stash m = silu(D2+b2) as bf16 in dead f-tile region
            if (ch == 0 && nh == 0){
                __nv_bfloat16* m0 = (__nv_bfloat16*)(sm + FAO);
                #pragma unroll
                for (int mt=0;mt<2;++mt){
                    int row = wm*32 + mt*16 + qr;
                    #pragma unroll
                    for (int nt=0;nt<8;++nt){
                        int col = wn*64 + nt*8 + 2*qc;   // global col (half 0)
                        float b0 = sm[MB2+col], b1c = sm[MB2+col+1];
                        m0[row*128 + col]       = __float2bfloat16(silu_f(c2[mt][nt][0]+b0));
                        m0[row*128 + col+1]     = __float2bfloat16(silu_f(c2[mt][nt][1]+b1c));
                        m0[(row+8)*128 + col]   = __float2bfloat16(silu_f(c2[mt][nt][2]+b0));
                        m0[(row+8)*128 + col+1] = __float2bfloat16(silu_f(c2[mt][nt][3]+b1c));
                    }
                }
            }

            if (nh == 1){
                __syncthreads();   // rowsum complete
                if (tid < NPN){
                    if (ch == 0)
                        sm[MWG+tid] = sigm_f(sm[MRS+tid] + battv) * sm[MAD+tid];
                    else
                        sm[MWG+tid] = (sm[MRS+tid] + bx3v) * sm[MRN+tid] * sm[MAD+tid];
                }
                __syncthreads();

                if (ch == 0){
                    // msg from live regs: cols 128..255
                    #pragma unroll
                    for (int nt=0;nt<8;++nt){
                        int colg = 128 + wn*64 + nt*8 + 2*qc;
                        float b0 = sm[MB2+colg], b1c = sm[MB2+colg+1];
                        float s0 = 0.f, s1 = 0.f;
                        #pragma unroll
                        for (int mt=0;mt<2;++mt){
                            int row = wm*32 + mt*16 + qr;
                            float w0 = sm[MWG+row], w8 = sm[MWG+row+8];
                            s0 += silu_f(c2[mt][nt][0]+b0 )*w0 + silu_f(c2[mt][nt][2]+b0 )*w8;
                            s1 += silu_f(c2[mt][nt][1]+b1c)*w0 + silu_f(c2[mt][nt][3]+b1c)*w8;
                        }
                        s0 += __shfl_xor_sync(0xffffffffu, s0, 4);
                        s0 += __shfl_xor_sync(0xffffffffu, s0, 8);
                        s0 += __shfl_xor_sync(0xffffffffu, s0, 16);
                        s1 += __shfl_xor_sync(0xffffffffu, s1, 4);
                        s1 += __shfl_xor_sync(0xffffffffu, s1, 8);
                        s1 += __shfl_xor_sync(0xffffffffu, s1, 16);
                        if (qr == 0){
                            atomicAdd(&sm[MMS+colg],   s0);
                            atomicAdd(&sm[MMS+colg+1], s1);
                        }
                    }
                    // msg from bf16 stash: cols 0..127
                    {
                        const __nv_bfloat16* m0 = (const __nv_bfloat16*)(sm + FAO);
                        int col = tid & 127;
                        int j0 = (tid >> 7) * 64;
                        float s = 0.f;
                        #pragma unroll 4
                        for (int j = j0; j < j0+64; ++j)
                            s += __bfloat162float(m0[j*128 + col]) * sm[MWG+j];
                        atomicAdd(&sm[MMS+col], s);
                    }
                } else {
                    if (warp < 4){
                        int j = warp*32 + lane;
                        float w = sm[MWG+j];
                        float a0 = sm[MDX+j]*w, a1 = sm[MDY+j]*w, a2 = sm[MDZ+j]*w;
                        #pragma unroll
                        for (int off=16; off>=1; off>>=1){
                            a0 += __shfl_down_sync(0xffffffffu, a0, off);
                            a1 += __shfl_down_sync(0xffffffffu, a1, off);
                            a2 += __shfl_down_sync(0xffffffffu, a2, off);
                        }
                        if (lane == 0){
                            atomicAdd(&sm[MCR+0], a0);
                            atomicAdd(&sm[MCR+1], a1);
                            atomicAdd(&sm[MCR+2], a2);
                        }
                    }
                }
                __syncthreads();
            }
        }
    }

    // ---- outputs ----
    g_msg[gi*D + tid] = sm[MMS + tid];
    if (tid < 3){
        float upd = sm[MCR+tid] / sm[MNN];
        outc[gi*3 + tid] = (coords[gi*3 + tid] + upd) * amask[gi];
    }
}

// =====================================================================
// node MLP: 8 nodes per CTA
// =====================================================================
__global__ void node_kernel(const float* __restrict__ inv, const float* __restrict__ amask,
                            const float* __restrict__ Wh1, const float* __restrict__ bh1,
                            const float* __restrict__ Wh2, const float* __restrict__ bh2,
                            float* __restrict__ outf)
{
    __shared__ float cat[8*2*D];
    __shared__ float h1[8*D];
    int g0 = blockIdx.x*8, c = threadIdx.x;
    #pragma unroll
    for (int r=0;r<8;++r){
        cat[r*2*D + c]     = inv[(g0+r)*D + c];
        cat[r*2*D + D + c] = g_msg[(g0+r)*D + c];
    }
    __syncthreads();
    float acc[8];
    float b1 = bh1[c];
    #pragma unroll
    for (int r=0;r<8;++r) acc[r]=b1;
    for (int k=0;k<2*D;++k){
        float w = Wh1[k*D+c];
        #pragma unroll
        for (int r=0;r<8;++r) acc[r] += cat[r*2*D + k]*w;
    }
    #pragma unroll
    for (int r=0;r<8;++r) h1[r*D+c] = silu_f(acc[r]);
    __syncthreads();
    float b2 = bh2[c];
    #pragma unroll
    for (int r=0;r<8;++r) acc[r]=b2;
    for (int k=0;k<D;++k){
        float w = Wh2[k*D+c];
        #pragma unroll
        for (int r=0;r<8;++r) acc[r] += h1[r*D+k]*w;
    }
    #pragma unroll
    for (int r=0;r<8;++r) outf[(g0+r)*D + c] = acc[r]*amask[g0+r];
}

// =====================================================================
extern "C" void kernel_launch(void* const* d_in, const int* in_sizes, int n_in,
                              void* d_out, int out_size)
{
    const float* coords = (const float*)d_in[0];
    const float* inv    = (const float*)d_in[1];
    const float* adj    = (const float*)d_in[2];
    const float* amask  = (const float*)d_in[3];
    const float* ef     = (const float*)d_in[4];
    const float* We1    = (const float*)d_in[5];
    const float* be1    = (const float*)d_in[6];
    const float* We2    = (const float*)d_in[7];
    const float* be2    = (const float*)d_in[8];
    const float* Watt   = (const float*)d_in[9];
    const float* batt   = (const float*)d_in[10];
    const float* Wh1    = (const float*)d_in[11];
    const float* bh1    = (const float*)d_in[12];
    const float* Wh2    = (const float*)d_in[13];
    const float* bh2    = (const float*)d_in[14];
    const float* Wx1    = (const float*)d_in[15];
    const float* bx1    = (const float*)d_in[16];
    const float* Wx2    = (const float*)d_in[17];
    const float* bx2    = (const float*)d_in[18];
    const float* Wx3    = (const float*)d_in[19];
    const float* bx3    = (const float*)d_in[20];

    float* out  = (float*)d_out;
    float* outc = out;            // [8,128,3]
    float* outf = out + GN*3;     // [8,128,256]

    cudaFuncSetAttribute(edge_kernel, cudaFuncAttributeMaxDynamicSharedMemorySize, SMEM_BYTES);

    prep_kernel<<<256, 256>>>(We1, Wx1, We2, Wx2);
    proj_kernel<<<GN/8, 256>>>(inv, We1, be1, Wx1, bx1);
    edge_kernel<<<GN, 256, SMEM_BYTES>>>(coords, adj, amask, ef,
                                         be2, Watt, batt, bx2, Wx3, bx3, outc);
    node_kernel<<<GN/8, 256>>>(inv, amask, Wh1, bh1, Wh2, bh2, outf);
}